// round 1
// baseline (speedup 1.0000x reference)
#include <cuda_runtime.h>
#include <cstdint>
#include <math.h>

#define T_STEPS 32768
#define H 256
#define G 32   // CTAs in the persistent scan; 8 j-owners (warps) per CTA

// ---------------- scratch (device globals: no allocation allowed) ----------------
__device__ __align__(16) float g_X[(size_t)T_STEPS * 1024];  // [t][m*256+j], m: 0=i,1=f,2=o,3=c
__device__ float g_decay[T_STEPS];
__device__ __align__(16) float g_h[2][H];
__device__ __align__(16) float g_c[2][H];
__device__ unsigned g_cnt;

// ---------------- init: reset barrier/state + compute decay ----------------
__global__ void init_kernel(const int* __restrict__ created)
{
    int t = blockIdx.x * blockDim.x + threadIdx.x;
    if (t == 0) g_cnt = 0u;
    if (t < H) {
        g_h[0][t] = 0.f; g_h[1][t] = 0.f;
        g_c[0][t] = 0.f; g_c[1][t] = 0.f;
    }
    if (t < T_STEPS) {
        float dt = (t == 0) ? 0.f : (float)(created[t] - created[t - 1]);
        g_decay[t] = 1.0f / logf(2.718281828459045f + dt);
    }
}

// ---------------- phase A: X[t, m*256+j] = inputs @ W_m + b_m ----------------
// grid (32 strips of 32 cols, 32 row chunks); W strip resident in smem per block.
__global__ void __launch_bounds__(256) xproj_kernel(
    const float* __restrict__ A,
    const float* __restrict__ Wi, const float* __restrict__ Wf,
    const float* __restrict__ Wo, const float* __restrict__ Wc,
    const float* __restrict__ bi, const float* __restrict__ bf,
    const float* __restrict__ bo, const float* __restrict__ bc)
{
    __shared__ __align__(16) float Wt[32][260];   // [col][k], padded: conflict-free float4 reads
    __shared__ __align__(16) float Asm[8][256];   // [row][k]

    const int s  = blockIdx.x;        // 0..31 ; 8 strips per gate matrix
    const int m  = s >> 3;            // which gate matrix
    const int j0 = (s & 7) * 32;      // column offset within the 256-wide gate
    const float* Wm = (m == 0) ? Wi : (m == 1) ? Wf : (m == 2) ? Wo : Wc;
    const float* bm = (m == 0) ? bi : (m == 1) ? bf : (m == 2) ? bo : bc;

    for (int i = threadIdx.x; i < 256 * 32; i += 256) {
        int k = i >> 5, jj = i & 31;
        Wt[jj][k] = Wm[k * 256 + j0 + jj];
    }
    const int col = threadIdx.x & 31;
    const int r   = threadIdx.x >> 5;
    const float bias = bm[j0 + col];
    const int rows_per_block = T_STEPS / 32;
    const int rbase = blockIdx.y * rows_per_block;
    __syncthreads();

    for (int it = 0; it < rows_per_block; it += 8) {
        const int r0 = rbase + it;
        for (int i = threadIdx.x; i < 8 * 256; i += 256) {
            int rr = i >> 8, k = i & 255;
            Asm[rr][k] = A[(size_t)(r0 + rr) * 256 + k];
        }
        __syncthreads();
        const float4* arow = (const float4*)(&Asm[r][0]);
        const float4* wrow = (const float4*)(&Wt[col][0]);
        float acc = bias;
        #pragma unroll 16
        for (int k4 = 0; k4 < 64; k4++) {
            float4 av = arow[k4];
            float4 wv = wrow[k4];
            acc = fmaf(av.x, wv.x, acc);
            acc = fmaf(av.y, wv.y, acc);
            acc = fmaf(av.z, wv.z, acc);
            acc = fmaf(av.w, wv.w, acc);
        }
        g_X[(size_t)(r0 + r) * 1024 + m * 256 + j0 + col] = acc;
        __syncthreads();
    }
}

// ---------------- phase B: persistent sequential scan ----------------
__device__ __forceinline__ float sigmoidf_(float x) { return 1.0f / (1.0f + expf(-x)); }

__global__ void __launch_bounds__(256) scan_kernel(
    const float* __restrict__ Ui, const float* __restrict__ Uf,
    const float* __restrict__ Uo, const float* __restrict__ Uc,
    const float* __restrict__ Wd, const float* __restrict__ bd,
    float* __restrict__ out)
{
    const int lane = threadIdx.x & 31;
    const int w    = threadIdx.x >> 5;        // warp = owner of one hidden index j
    const int j    = blockIdx.x * 8 + w;      // 32 CTAs * 8 warps = 256 = H

    // Weight columns for this j live in registers for the whole scan.
    // lane covers k = lane*8 .. lane*8+7 (matches the float4 h/c loads below).
    float wi[8], wf[8], wo[8], wc[8], wd[8];
    #pragma unroll
    for (int u = 0; u < 8; u++) {
        int k = lane * 8 + u;
        wi[u] = Ui[k * H + j];
        wf[u] = Uf[k * H + j];
        wo[u] = Uo[k * H + j];
        wc[u] = Uc[k * H + j];
        wd[u] = Wd[k * H + j];
    }
    const float bdj = bd[j];

    // x / decay for t=0 (prefetched one step ahead thereafter)
    float xi = g_X[j], xf = g_X[256 + j], xo = g_X[512 + j], xc = g_X[768 + j];
    float dec = g_decay[0];

    for (int t = 0; t < T_STEPS; t++) {
        const int p = t & 1;
        const float4* hb4 = (const float4*)(&g_h[p][0]);
        const float4* cb4 = (const float4*)(&g_c[p][0]);
        // L2-coherent (bypass L1) reads of the broadcast state
        float4 h0 = __ldcg(hb4 + lane * 2);
        float4 h1 = __ldcg(hb4 + lane * 2 + 1);
        float4 c0 = __ldcg(cb4 + lane * 2);
        float4 c1 = __ldcg(cb4 + lane * 2 + 1);
        float cprev = __ldcg(&g_c[p][j]);

        // prefetch next step's x/decay (independent of the recurrence)
        float nxi = 0.f, nxf = 0.f, nxo = 0.f, nxc = 0.f, ndec = 0.f;
        if (t + 1 < T_STEPS) {
            const float* Xn = g_X + (size_t)(t + 1) * 1024;
            nxi = Xn[j]; nxf = Xn[256 + j]; nxo = Xn[512 + j]; nxc = Xn[768 + j];
            ndec = g_decay[t + 1];
        }

        float hv[8] = {h0.x, h0.y, h0.z, h0.w, h1.x, h1.y, h1.z, h1.w};
        float cv[8] = {c0.x, c0.y, c0.z, c0.w, c1.x, c1.y, c1.z, c1.w};
        float aI = 0.f, aF = 0.f, aO = 0.f, aC = 0.f, aS = 0.f;
        #pragma unroll
        for (int u = 0; u < 8; u++) {
            aI = fmaf(hv[u], wi[u], aI);
            aF = fmaf(hv[u], wf[u], aF);
            aO = fmaf(hv[u], wo[u], aO);
            aC = fmaf(hv[u], wc[u], aC);
            aS = fmaf(cv[u], wd[u], aS);
        }
        #pragma unroll
        for (int off = 16; off > 0; off >>= 1) {
            aI += __shfl_xor_sync(0xffffffffu, aI, off);
            aF += __shfl_xor_sync(0xffffffffu, aF, off);
            aO += __shfl_xor_sync(0xffffffffu, aO, off);
            aC += __shfl_xor_sync(0xffffffffu, aC, off);
            aS += __shfl_xor_sync(0xffffffffu, aS, off);
        }

        float s_  = tanhf(aS + bdj);
        float adj = (cprev - s_) + s_ * dec;
        float ig  = sigmoidf_(xi + aI);
        float fg  = sigmoidf_(xf + aF);
        float og  = sigmoidf_(xo + aO);
        float gg  = tanhf(xc + aC);
        float cnew = fg * adj + ig * gg;
        float hnew = og * tanhf(cprev);   // faithful: uses previous memory

        if (lane == 0) {
            out[(size_t)t * H + j] = hnew;
            g_h[p ^ 1][j] = hnew;
            g_c[p ^ 1][j] = cnew;
        }
        xi = nxi; xf = nxf; xo = nxo; xc = nxc; dec = ndec;

        // one release/acquire barrier per step across the G CTAs
        __syncthreads();
        if (threadIdx.x == 0) {
            __threadfence();                 // release: slice writes visible before arrive
            atomicAdd(&g_cnt, 1u);
            const unsigned target = (unsigned)(t + 1) * (unsigned)G;
            unsigned v;
            do {
                asm volatile("ld.acquire.gpu.global.u32 %0, [%1];"
                             : "=r"(v) : "l"(&g_cnt) : "memory");
            } while (v < target);
        }
        __syncthreads();
    }
}

// ---------------- launch ----------------
extern "C" void kernel_launch(void* const* d_in, const int* in_sizes, int n_in,
                              void* d_out, int out_size)
{
    const float* inputs  = (const float*)d_in[0];
    const int*   created = (const int*)  d_in[1];
    const float* W_d = (const float*)d_in[2];
    /* U_d (d_in[3]) is unused by the reference */
    const float* b_d = (const float*)d_in[4];
    const float* W_f = (const float*)d_in[5];
    const float* U_f = (const float*)d_in[6];
    const float* b_f = (const float*)d_in[7];
    const float* W_i = (const float*)d_in[8];
    const float* U_i = (const float*)d_in[9];
    const float* b_i = (const float*)d_in[10];
    const float* W_o = (const float*)d_in[11];
    const float* U_o = (const float*)d_in[12];
    const float* b_o = (const float*)d_in[13];
    const float* W_c = (const float*)d_in[14];
    const float* U_c = (const float*)d_in[15];
    const float* b_c = (const float*)d_in[16];
    float* out = (float*)d_out;

    init_kernel<<<(T_STEPS + 255) / 256, 256>>>(created);
    xproj_kernel<<<dim3(32, 32), 256>>>(inputs, W_i, W_f, W_o, W_c,
                                        b_i, b_f, b_o, b_c);
    scan_kernel<<<G, 256>>>(U_i, U_f, U_o, U_c, W_d, b_d, out);
}

// round 2
// speedup vs baseline: 1.0669x; 1.0669x over previous
#include <cuda_runtime.h>
#include <cstdint>
#include <math.h>

#define T_STEPS 32768
#define H 256
#define G 32   // CTAs in the persistent scan; 8 j-owners (warps) per CTA

// ---------------- scratch (device globals: no allocation allowed) ----------------
__device__ __align__(16) float g_X[(size_t)T_STEPS * 1024];  // [t][m*256+j], m: 0=i,1=f,2=o,3=c
__device__ float g_decay[T_STEPS];
__device__ __align__(16) float g_h[2][H];
__device__ __align__(16) float g_c[2][H];
__device__ __align__(128) unsigned g_flag[G * 32];   // one flag per CTA, 128B apart

// ---------------- init: reset flags/state + compute decay ----------------
__global__ void init_kernel(const int* __restrict__ created)
{
    int t = blockIdx.x * blockDim.x + threadIdx.x;
    if (t < G * 32) g_flag[t] = 0u;
    if (t < H) {
        g_h[0][t] = 0.f; g_h[1][t] = 0.f;
        g_c[0][t] = 0.f; g_c[1][t] = 0.f;
    }
    if (t < T_STEPS) {
        float dt = (t == 0) ? 0.f : (float)(created[t] - created[t - 1]);
        g_decay[t] = 1.0f / logf(2.718281828459045f + dt);
    }
}

// ---------------- phase A: X[t, m*256+j] = inputs @ W_m + b_m ----------------
__global__ void __launch_bounds__(256) xproj_kernel(
    const float* __restrict__ A,
    const float* __restrict__ Wi, const float* __restrict__ Wf,
    const float* __restrict__ Wo, const float* __restrict__ Wc,
    const float* __restrict__ bi, const float* __restrict__ bf,
    const float* __restrict__ bo, const float* __restrict__ bc)
{
    __shared__ __align__(16) float Wt[32][260];   // [col][k], padded
    __shared__ __align__(16) float Asm[8][256];   // [row][k]

    const int s  = blockIdx.x;        // 0..31 ; 8 strips per gate matrix
    const int m  = s >> 3;
    const int j0 = (s & 7) * 32;
    const float* Wm = (m == 0) ? Wi : (m == 1) ? Wf : (m == 2) ? Wo : Wc;
    const float* bm = (m == 0) ? bi : (m == 1) ? bf : (m == 2) ? bo : bc;

    for (int i = threadIdx.x; i < 256 * 32; i += 256) {
        int k = i >> 5, jj = i & 31;
        Wt[jj][k] = Wm[k * 256 + j0 + jj];
    }
    const int col = threadIdx.x & 31;
    const int r   = threadIdx.x >> 5;
    const float bias = bm[j0 + col];
    const int rows_per_block = T_STEPS / 32;
    const int rbase = blockIdx.y * rows_per_block;
    __syncthreads();

    for (int it = 0; it < rows_per_block; it += 8) {
        const int r0 = rbase + it;
        for (int i = threadIdx.x; i < 8 * 256; i += 256) {
            int rr = i >> 8, k = i & 255;
            Asm[rr][k] = A[(size_t)(r0 + rr) * 256 + k];
        }
        __syncthreads();
        const float4* arow = (const float4*)(&Asm[r][0]);
        const float4* wrow = (const float4*)(&Wt[col][0]);
        float acc = bias;
        #pragma unroll 16
        for (int k4 = 0; k4 < 64; k4++) {
            float4 av = arow[k4];
            float4 wv = wrow[k4];
            acc = fmaf(av.x, wv.x, acc);
            acc = fmaf(av.y, wv.y, acc);
            acc = fmaf(av.z, wv.z, acc);
            acc = fmaf(av.w, wv.w, acc);
        }
        g_X[(size_t)(r0 + r) * 1024 + m * 256 + j0 + col] = acc;
        __syncthreads();
    }
}

// ---------------- phase B: persistent sequential scan ----------------
__device__ __forceinline__ float tanh_fast(float x) {
    float y;
    asm("tanh.approx.f32 %0, %1;" : "=f"(y) : "f"(x));
    return y;
}
__device__ __forceinline__ float sigmoid_fast(float x) {
    return fmaf(tanh_fast(0.5f * x), 0.5f, 0.5f);
}

__global__ void __launch_bounds__(256) scan_kernel(
    const float* __restrict__ Ui, const float* __restrict__ Uf,
    const float* __restrict__ Uo, const float* __restrict__ Uc,
    const float* __restrict__ Wd, const float* __restrict__ bd,
    float* __restrict__ out)
{
    const int lane = threadIdx.x & 31;
    const int w    = threadIdx.x >> 5;        // warp = owner of one hidden index j
    const int j    = blockIdx.x * 8 + w;      // 32 CTAs * 8 warps = 256 = H

    // Weight columns for this j live in registers for the whole scan.
    float wi[8], wf[8], wo[8], wc[8], wd[8];
    #pragma unroll
    for (int u = 0; u < 8; u++) {
        int k = lane * 8 + u;
        wi[u] = Ui[k * H + j];
        wf[u] = Uf[k * H + j];
        wo[u] = Uo[k * H + j];
        wc[u] = Uc[k * H + j];
        wd[u] = Wd[k * H + j];
    }
    const float bdj = bd[j];

    float xi = g_X[j], xf = g_X[256 + j], xo = g_X[512 + j], xc = g_X[768 + j];
    float dec = g_decay[0];

    unsigned* const my_flag = g_flag + blockIdx.x * 32;

    for (int t = 0; t < T_STEPS; t++) {
        // ---- wait: all CTAs finished step t-1 (flag >= t). warp 0 polls. ----
        if (w == 0) {
            const unsigned target = (unsigned)t;
            unsigned v = target;
            bool done;
            do {
                if (lane < G) {
                    asm volatile("ld.acquire.gpu.global.u32 %0, [%1];"
                                 : "=r"(v) : "l"(g_flag + lane * 32) : "memory");
                }
                done = __all_sync(0xffffffffu, v >= target);
            } while (!done);
        }
        __syncthreads();

        const int p = t & 1;
        const float4* hb4 = (const float4*)(&g_h[p][0]);
        const float4* cb4 = (const float4*)(&g_c[p][0]);
        float4 h0 = __ldcg(hb4 + lane * 2);
        float4 h1 = __ldcg(hb4 + lane * 2 + 1);
        float4 c0 = __ldcg(cb4 + lane * 2);
        float4 c1 = __ldcg(cb4 + lane * 2 + 1);
        float cprev = __ldcg(&g_c[p][j]);
        float tanh_cprev = tanh_fast(cprev);     // off the reduce critical path

        // prefetch next step's x/decay (independent of the recurrence)
        float nxi = 0.f, nxf = 0.f, nxo = 0.f, nxc = 0.f, ndec = 0.f;
        if (t + 1 < T_STEPS) {
            const float* Xn = g_X + (size_t)(t + 1) * 1024;
            nxi = Xn[j]; nxf = Xn[256 + j]; nxo = Xn[512 + j]; nxc = Xn[768 + j];
            ndec = g_decay[t + 1];
        }

        float hv[8] = {h0.x, h0.y, h0.z, h0.w, h1.x, h1.y, h1.z, h1.w};
        float cv[8] = {c0.x, c0.y, c0.z, c0.w, c1.x, c1.y, c1.z, c1.w};
        float aI = 0.f, aF = 0.f, aO = 0.f, aC = 0.f, aS = 0.f;
        #pragma unroll
        for (int u = 0; u < 8; u++) {
            aI = fmaf(hv[u], wi[u], aI);
            aF = fmaf(hv[u], wf[u], aF);
            aO = fmaf(hv[u], wo[u], aO);
            aC = fmaf(hv[u], wc[u], aC);
            aS = fmaf(cv[u], wd[u], aS);
        }
        #pragma unroll
        for (int off = 16; off > 0; off >>= 1) {
            aI += __shfl_xor_sync(0xffffffffu, aI, off);
            aF += __shfl_xor_sync(0xffffffffu, aF, off);
            aO += __shfl_xor_sync(0xffffffffu, aO, off);
            aC += __shfl_xor_sync(0xffffffffu, aC, off);
            aS += __shfl_xor_sync(0xffffffffu, aS, off);
        }

        float s_  = tanh_fast(aS + bdj);
        float adj = (cprev - s_) + s_ * dec;
        float ig  = sigmoid_fast(xi + aI);
        float fg  = sigmoid_fast(xf + aF);
        float og  = sigmoid_fast(xo + aO);
        float gg  = tanh_fast(xc + aC);
        float cnew = fg * adj + ig * gg;
        float hnew = og * tanh_cprev;            // faithful: uses previous memory

        if (lane == 0) {
            out[(size_t)t * H + j] = hnew;
            g_h[p ^ 1][j] = hnew;
            g_c[p ^ 1][j] = cnew;
        }
        xi = nxi; xf = nxf; xo = nxo; xc = nxc; dec = ndec;

        // ---- publish: all warps' stores done -> fence -> flag = t+1 ----
        __syncthreads();
        if (threadIdx.x == 0) {
            asm volatile("fence.acq_rel.gpu;" ::: "memory");
            asm volatile("st.relaxed.gpu.global.u32 [%0], %1;"
                         :: "l"(my_flag), "r"((unsigned)(t + 1)) : "memory");
        }
    }
}

// ---------------- launch ----------------
extern "C" void kernel_launch(void* const* d_in, const int* in_sizes, int n_in,
                              void* d_out, int out_size)
{
    const float* inputs  = (const float*)d_in[0];
    const int*   created = (const int*)  d_in[1];
    const float* W_d = (const float*)d_in[2];
    /* U_d (d_in[3]) is unused by the reference */
    const float* b_d = (const float*)d_in[4];
    const float* W_f = (const float*)d_in[5];
    const float* U_f = (const float*)d_in[6];
    const float* b_f = (const float*)d_in[7];
    const float* W_i = (const float*)d_in[8];
    const float* U_i = (const float*)d_in[9];
    const float* b_i = (const float*)d_in[10];
    const float* W_o = (const float*)d_in[11];
    const float* U_o = (const float*)d_in[12];
    const float* b_o = (const float*)d_in[13];
    const float* W_c = (const float*)d_in[14];
    const float* U_c = (const float*)d_in[15];
    const float* b_c = (const float*)d_in[16];
    float* out = (float*)d_out;

    init_kernel<<<(T_STEPS + 255) / 256, 256>>>(created);
    xproj_kernel<<<dim3(32, 32), 256>>>(inputs, W_i, W_f, W_o, W_c,
                                        b_i, b_f, b_o, b_c);
    scan_kernel<<<G, 256>>>(U_i, U_f, U_o, U_c, W_d, b_d, out);
}

// round 3
// speedup vs baseline: 1.3453x; 1.2609x over previous
#include <cuda_runtime.h>
#include <cstdint>
#include <math.h>

#define T_STEPS 32768
#define H 256
#define GFB 32   // CTAs in the fallback global-sync scan

// ---------------- scratch (device globals: no allocation allowed) ----------------
__device__ __align__(16) float g_X[(size_t)T_STEPS * 1024];  // [t][m*256+j], m: 0=i,1=f,2=o,3=c
__device__ float g_decay[T_STEPS];
__device__ __align__(16) float g_h[2][H];                    // fallback path state
__device__ __align__(16) float g_c[2][H];
__device__ __align__(128) unsigned g_flag[GFB * 32];         // fallback flags, 128B apart

// ---------------- init ----------------
__global__ void init_kernel(const int* __restrict__ created)
{
    int t = blockIdx.x * blockDim.x + threadIdx.x;
    if (t < GFB * 32) g_flag[t] = 0u;
    if (t < H) {
        g_h[0][t] = 0.f; g_h[1][t] = 0.f;
        g_c[0][t] = 0.f; g_c[1][t] = 0.f;
    }
    if (t < T_STEPS) {
        float dt = (t == 0) ? 0.f : (float)(created[t] - created[t - 1]);
        g_decay[t] = 1.0f / logf(2.718281828459045f + dt);
    }
}

// ---------------- phase A: X[t, m*256+j] = inputs @ W_m + b_m ----------------
__global__ void __launch_bounds__(256) xproj_kernel(
    const float* __restrict__ A,
    const float* __restrict__ Wi, const float* __restrict__ Wf,
    const float* __restrict__ Wo, const float* __restrict__ Wc,
    const float* __restrict__ bi, const float* __restrict__ bf,
    const float* __restrict__ bo, const float* __restrict__ bc)
{
    __shared__ __align__(16) float Wt[32][260];
    __shared__ __align__(16) float Asm[8][256];

    const int s  = blockIdx.x;
    const int m  = s >> 3;
    const int j0 = (s & 7) * 32;
    const float* Wm = (m == 0) ? Wi : (m == 1) ? Wf : (m == 2) ? Wo : Wc;
    const float* bm = (m == 0) ? bi : (m == 1) ? bf : (m == 2) ? bo : bc;

    for (int i = threadIdx.x; i < 256 * 32; i += 256) {
        int k = i >> 5, jj = i & 31;
        Wt[jj][k] = Wm[k * 256 + j0 + jj];
    }
    const int col = threadIdx.x & 31;
    const int r   = threadIdx.x >> 5;
    const float bias = bm[j0 + col];
    const int rows_per_block = T_STEPS / 32;
    const int rbase = blockIdx.y * rows_per_block;
    __syncthreads();

    for (int it = 0; it < rows_per_block; it += 8) {
        const int r0 = rbase + it;
        for (int i = threadIdx.x; i < 8 * 256; i += 256) {
            int rr = i >> 8, k = i & 255;
            Asm[rr][k] = A[(size_t)(r0 + rr) * 256 + k];
        }
        __syncthreads();
        const float4* arow = (const float4*)(&Asm[r][0]);
        const float4* wrow = (const float4*)(&Wt[col][0]);
        float acc = bias;
        #pragma unroll 16
        for (int k4 = 0; k4 < 64; k4++) {
            float4 av = arow[k4];
            float4 wv = wrow[k4];
            acc = fmaf(av.x, wv.x, acc);
            acc = fmaf(av.y, wv.y, acc);
            acc = fmaf(av.z, wv.z, acc);
            acc = fmaf(av.w, wv.w, acc);
        }
        g_X[(size_t)(r0 + r) * 1024 + m * 256 + j0 + col] = acc;
        __syncthreads();
    }
}

// ---------------- helpers ----------------
__device__ __forceinline__ float tanh_fast(float x) {
    float y;
    asm("tanh.approx.f32 %0, %1;" : "=f"(y) : "f"(x));
    return y;
}
__device__ __forceinline__ float sigmoid_fast(float x) {
    return fmaf(tanh_fast(0.5f * x), 0.5f, 0.5f);
}
__device__ __forceinline__ unsigned smem_u32(const void* p) {
    return (unsigned)__cvta_generic_to_shared(p);
}
__device__ __forceinline__ void dsmem_store_pair(unsigned local_addr, unsigned rank,
                                                 float h, float c) {
    float2 v = make_float2(h, c);
    unsigned long long u;
    asm("mov.b64 %0, {%1, %2};" : "=l"(u) : "f"(v.x), "f"(v.y));
    unsigned remote;
    asm volatile("mapa.shared::cluster.u32 %0, %1, %2;"
                 : "=r"(remote) : "r"(local_addr), "r"(rank));
    asm volatile("st.shared::cluster.u64 [%0], %1;" :: "r"(remote), "l"(u) : "memory");
}

// ---------------- phase B (fast): cluster scan with DSMEM broadcast ----------------
// CS CTAs x 512 threads (16 warps). Warp w owns NJ hidden indices:
//   j = rank*(16*NJ) + w + n*16.  Weight columns in registers.
// State (h,c) pairs replicated in every CTA's smem, double-buffered by parity.
// One barrier.cluster per step (arrive has release, wait has acquire semantics).
template<int CS, int NJ>
__global__ void __launch_bounds__(512, 1) scan_cluster_kernel(
    const float* __restrict__ Ui, const float* __restrict__ Uf,
    const float* __restrict__ Uo, const float* __restrict__ Uc,
    const float* __restrict__ Wd, const float* __restrict__ bd,
    float* __restrict__ out)
{
    __shared__ __align__(16) float2 hc[2][H];   // (h, c) interleaved

    const int lane = threadIdx.x & 31;
    const int w    = threadIdx.x >> 5;          // 0..15
    unsigned rank;
    asm("mov.u32 %0, %%cluster_ctarank;" : "=r"(rank));

    int jj[NJ];
    #pragma unroll
    for (int n = 0; n < NJ; n++) jj[n] = (int)rank * (16 * NJ) + w + n * 16;

    // Weight columns for this warp's j's, k-sliced over lanes (k = lane*8 + u).
    float wi[NJ][8], wf[NJ][8], wo[NJ][8], wc[NJ][8], wd_[NJ][8], bdj[NJ];
    #pragma unroll
    for (int n = 0; n < NJ; n++) {
        #pragma unroll
        for (int u = 0; u < 8; u++) {
            int k = lane * 8 + u;
            wi[n][u]  = Ui[k * H + jj[n]];
            wf[n][u]  = Uf[k * H + jj[n]];
            wo[n][u]  = Uo[k * H + jj[n]];
            wc[n][u]  = Uc[k * H + jj[n]];
            wd_[n][u] = Wd[k * H + jj[n]];
        }
        bdj[n] = bd[jj[n]];
    }

    // zero both state slots, then cluster-wide rendezvous
    for (int i = threadIdx.x; i < 2 * H; i += 512)
        ((float2*)hc)[i] = make_float2(0.f, 0.f);
    __syncthreads();
    asm volatile("barrier.cluster.arrive.aligned;" ::: "memory");
    asm volatile("barrier.cluster.wait.aligned;"   ::: "memory");

    // x / decay for t=0 (prefetched one step ahead thereafter, inside barrier window)
    float xi[NJ], xf[NJ], xo[NJ], xc[NJ];
    #pragma unroll
    for (int n = 0; n < NJ; n++) {
        xi[n] = g_X[jj[n]]; xf[n] = g_X[256 + jj[n]];
        xo[n] = g_X[512 + jj[n]]; xc[n] = g_X[768 + jj[n]];
    }
    float dec = g_decay[0];

    for (int t = 0; t < T_STEPS; t++) {
        const int p = t & 1;

        // read broadcast state from LOCAL smem (written remotely last step)
        const float4* b4 = (const float4*)(&hc[p][lane * 8]);
        float4 q0 = b4[0], q1 = b4[1], q2 = b4[2], q3 = b4[3];
        float hv[8] = {q0.x, q0.z, q1.x, q1.z, q2.x, q2.z, q3.x, q3.z};
        float cv[8] = {q0.y, q0.w, q1.y, q1.w, q2.y, q2.w, q3.y, q3.w};

        float cprev[NJ], tcp[NJ];
        #pragma unroll
        for (int n = 0; n < NJ; n++) {
            cprev[n] = hc[p][jj[n]].y;
            tcp[n]   = tanh_fast(cprev[n]);
        }

        float aI[NJ], aF[NJ], aO[NJ], aC[NJ], aS[NJ];
        #pragma unroll
        for (int n = 0; n < NJ; n++) { aI[n]=0.f; aF[n]=0.f; aO[n]=0.f; aC[n]=0.f; aS[n]=0.f; }
        #pragma unroll
        for (int u = 0; u < 8; u++) {
            #pragma unroll
            for (int n = 0; n < NJ; n++) {
                aI[n] = fmaf(hv[u], wi[n][u],  aI[n]);
                aF[n] = fmaf(hv[u], wf[n][u],  aF[n]);
                aO[n] = fmaf(hv[u], wo[n][u],  aO[n]);
                aC[n] = fmaf(hv[u], wc[n][u],  aC[n]);
                aS[n] = fmaf(cv[u], wd_[n][u], aS[n]);
            }
        }
        #pragma unroll
        for (int off = 16; off > 0; off >>= 1) {
            #pragma unroll
            for (int n = 0; n < NJ; n++) {
                aI[n] += __shfl_xor_sync(0xffffffffu, aI[n], off);
                aF[n] += __shfl_xor_sync(0xffffffffu, aF[n], off);
                aO[n] += __shfl_xor_sync(0xffffffffu, aO[n], off);
                aC[n] += __shfl_xor_sync(0xffffffffu, aC[n], off);
                aS[n] += __shfl_xor_sync(0xffffffffu, aS[n], off);
            }
        }

        float hnew[NJ], cnew[NJ];
        #pragma unroll
        for (int n = 0; n < NJ; n++) {
            float s_  = tanh_fast(aS[n] + bdj[n]);
            float adj = (cprev[n] - s_) + s_ * dec;
            float ig  = sigmoid_fast(xi[n] + aI[n]);
            float fg  = sigmoid_fast(xf[n] + aF[n]);
            float og  = sigmoid_fast(xo[n] + aO[n]);
            float gg  = tanh_fast(xc[n] + aC[n]);
            cnew[n] = fg * adj + ig * gg;
            hnew[n] = og * tcp[n];               // faithful: uses previous memory
        }

        // push (h,c) into every cluster CTA's slot p^1; lane l targets rank l
        if (lane < CS) {
            #pragma unroll
            for (int n = 0; n < NJ; n++) {
                unsigned laddr = smem_u32(&hc[p ^ 1][jj[n]]);
                dsmem_store_pair(laddr, (unsigned)lane, hnew[n], cnew[n]);
            }
        }

        // release our stores to the cluster
        asm volatile("barrier.cluster.arrive.aligned;" ::: "memory");

        // hide inside the barrier window: output store + next-step x/decay prefetch
        if (lane == 0) {
            #pragma unroll
            for (int n = 0; n < NJ; n++)
                out[(size_t)t * H + jj[n]] = hnew[n];
        }
        float nxi[NJ], nxf[NJ], nxo[NJ], nxc[NJ], ndec = 0.f;
        #pragma unroll
        for (int n = 0; n < NJ; n++) { nxi[n]=0.f; nxf[n]=0.f; nxo[n]=0.f; nxc[n]=0.f; }
        if (t + 1 < T_STEPS) {
            const float* Xn = g_X + (size_t)(t + 1) * 1024;
            #pragma unroll
            for (int n = 0; n < NJ; n++) {
                nxi[n] = Xn[jj[n]]; nxf[n] = Xn[256 + jj[n]];
                nxo[n] = Xn[512 + jj[n]]; nxc[n] = Xn[768 + jj[n]];
            }
            ndec = g_decay[t + 1];
        }

        asm volatile("barrier.cluster.wait.aligned;" ::: "memory");

        #pragma unroll
        for (int n = 0; n < NJ; n++) { xi[n]=nxi[n]; xf[n]=nxf[n]; xo[n]=nxo[n]; xc[n]=nxc[n]; }
        dec = ndec;
    }
}

// ---------------- phase B (fallback): global-sync persistent scan ----------------
__global__ void __launch_bounds__(256) scan_global_kernel(
    const float* __restrict__ Ui, const float* __restrict__ Uf,
    const float* __restrict__ Uo, const float* __restrict__ Uc,
    const float* __restrict__ Wd, const float* __restrict__ bd,
    float* __restrict__ out)
{
    const int lane = threadIdx.x & 31;
    const int w    = threadIdx.x >> 5;
    const int j    = blockIdx.x * 8 + w;

    float wi[8], wf[8], wo[8], wc[8], wd[8];
    #pragma unroll
    for (int u = 0; u < 8; u++) {
        int k = lane * 8 + u;
        wi[u] = Ui[k * H + j];
        wf[u] = Uf[k * H + j];
        wo[u] = Uo[k * H + j];
        wc[u] = Uc[k * H + j];
        wd[u] = Wd[k * H + j];
    }
    const float bdj = bd[j];

    float xi = g_X[j], xf = g_X[256 + j], xo = g_X[512 + j], xc = g_X[768 + j];
    float dec = g_decay[0];
    unsigned* const my_flag = g_flag + blockIdx.x * 32;

    for (int t = 0; t < T_STEPS; t++) {
        if (w == 0) {
            const unsigned target = (unsigned)t;
            unsigned v = target;
            bool done;
            do {
                if (lane < GFB) {
                    asm volatile("ld.acquire.gpu.global.u32 %0, [%1];"
                                 : "=r"(v) : "l"(g_flag + lane * 32) : "memory");
                }
                done = __all_sync(0xffffffffu, v >= target);
            } while (!done);
        }
        __syncthreads();

        const int p = t & 1;
        const float4* hb4 = (const float4*)(&g_h[p][0]);
        const float4* cb4 = (const float4*)(&g_c[p][0]);
        float4 h0 = __ldcg(hb4 + lane * 2);
        float4 h1 = __ldcg(hb4 + lane * 2 + 1);
        float4 c0 = __ldcg(cb4 + lane * 2);
        float4 c1 = __ldcg(cb4 + lane * 2 + 1);
        float cprev = __ldcg(&g_c[p][j]);
        float tanh_cprev = tanh_fast(cprev);

        float nxi = 0.f, nxf = 0.f, nxo = 0.f, nxc = 0.f, ndec = 0.f;
        if (t + 1 < T_STEPS) {
            const float* Xn = g_X + (size_t)(t + 1) * 1024;
            nxi = Xn[j]; nxf = Xn[256 + j]; nxo = Xn[512 + j]; nxc = Xn[768 + j];
            ndec = g_decay[t + 1];
        }

        float hv[8] = {h0.x, h0.y, h0.z, h0.w, h1.x, h1.y, h1.z, h1.w};
        float cv[8] = {c0.x, c0.y, c0.z, c0.w, c1.x, c1.y, c1.z, c1.w};
        float aI = 0.f, aF = 0.f, aO = 0.f, aC = 0.f, aS = 0.f;
        #pragma unroll
        for (int u = 0; u < 8; u++) {
            aI = fmaf(hv[u], wi[u], aI);
            aF = fmaf(hv[u], wf[u], aF);
            aO = fmaf(hv[u], wo[u], aO);
            aC = fmaf(hv[u], wc[u], aC);
            aS = fmaf(cv[u], wd[u], aS);
        }
        #pragma unroll
        for (int off = 16; off > 0; off >>= 1) {
            aI += __shfl_xor_sync(0xffffffffu, aI, off);
            aF += __shfl_xor_sync(0xffffffffu, aF, off);
            aO += __shfl_xor_sync(0xffffffffu, aO, off);
            aC += __shfl_xor_sync(0xffffffffu, aC, off);
            aS += __shfl_xor_sync(0xffffffffu, aS, off);
        }

        float s_  = tanh_fast(aS + bdj);
        float adj = (cprev - s_) + s_ * dec;
        float ig  = sigmoid_fast(xi + aI);
        float fg  = sigmoid_fast(xf + aF);
        float og  = sigmoid_fast(xo + aO);
        float gg  = tanh_fast(xc + aC);
        float cnew = fg * adj + ig * gg;
        float hnew = og * tanh_cprev;

        if (lane == 0) {
            out[(size_t)t * H + j] = hnew;
            g_h[p ^ 1][j] = hnew;
            g_c[p ^ 1][j] = cnew;
        }
        xi = nxi; xf = nxf; xo = nxo; xc = nxc; dec = ndec;

        __syncthreads();
        if (threadIdx.x == 0) {
            asm volatile("fence.acq_rel.gpu;" ::: "memory");
            asm volatile("st.relaxed.gpu.global.u32 [%0], %1;"
                         :: "l"(my_flag), "r"((unsigned)(t + 1)) : "memory");
        }
    }
}

// ---------------- launch ----------------
extern "C" void kernel_launch(void* const* d_in, const int* in_sizes, int n_in,
                              void* d_out, int out_size)
{
    const float* inputs  = (const float*)d_in[0];
    const int*   created = (const int*)  d_in[1];
    const float* W_d = (const float*)d_in[2];
    /* U_d (d_in[3]) is unused by the reference */
    const float* b_d = (const float*)d_in[4];
    const float* W_f = (const float*)d_in[5];
    const float* U_f = (const float*)d_in[6];
    const float* b_f = (const float*)d_in[7];
    const float* W_i = (const float*)d_in[8];
    const float* U_i = (const float*)d_in[9];
    const float* b_i = (const float*)d_in[10];
    const float* W_o = (const float*)d_in[11];
    const float* U_o = (const float*)d_in[12];
    const float* b_o = (const float*)d_in[13];
    const float* W_c = (const float*)d_in[14];
    const float* U_c = (const float*)d_in[15];
    const float* b_c = (const float*)d_in[16];
    float* out = (float*)d_out;

    init_kernel<<<(T_STEPS + 255) / 256, 256>>>(created);
    xproj_kernel<<<dim3(32, 32), 256>>>(inputs, W_i, W_f, W_o, W_c,
                                        b_i, b_f, b_o, b_c);

    // Decide cluster support (pure occupancy queries — capture-safe, deterministic).
    int maxc16 = 0, maxc8 = 0;
    {
        cudaFuncSetAttribute(scan_cluster_kernel<16, 1>,
                             cudaFuncAttributeNonPortableClusterSizeAllowed, 1);
        cudaLaunchConfig_t q = {};
        q.gridDim = dim3(16, 1, 1); q.blockDim = dim3(512, 1, 1);
        q.dynamicSmemBytes = 0; q.stream = 0; q.attrs = nullptr; q.numAttrs = 0;
        cudaOccupancyMaxPotentialClusterSize(&maxc16, scan_cluster_kernel<16, 1>, &q);
        cudaLaunchConfig_t q8 = q;
        q8.gridDim = dim3(8, 1, 1);
        cudaOccupancyMaxPotentialClusterSize(&maxc8, scan_cluster_kernel<8, 2>, &q8);
    }

    if (maxc16 >= 16) {
        cudaLaunchConfig_t cfg = {};
        cfg.gridDim  = dim3(16, 1, 1);
        cfg.blockDim = dim3(512, 1, 1);
        cfg.dynamicSmemBytes = 0;
        cfg.stream = 0;
        cudaLaunchAttribute at[1];
        at[0].id = cudaLaunchAttributeClusterDimension;
        at[0].val.clusterDim = {16, 1, 1};
        cfg.attrs = at; cfg.numAttrs = 1;
        cudaLaunchKernelEx(&cfg, scan_cluster_kernel<16, 1>,
                           U_i, U_f, U_o, U_c, W_d, b_d, out);
    } else if (maxc8 >= 8) {
        cudaLaunchConfig_t cfg = {};
        cfg.gridDim  = dim3(8, 1, 1);
        cfg.blockDim = dim3(512, 1, 1);
        cfg.dynamicSmemBytes = 0;
        cfg.stream = 0;
        cudaLaunchAttribute at[1];
        at[0].id = cudaLaunchAttributeClusterDimension;
        at[0].val.clusterDim = {8, 1, 1};
        cfg.attrs = at; cfg.numAttrs = 1;
        cudaLaunchKernelEx(&cfg, scan_cluster_kernel<8, 2>,
                           U_i, U_f, U_o, U_c, W_d, b_d, out);
    } else {
        scan_global_kernel<<<GFB, 256>>>(U_i, U_f, U_o, U_c, W_d, b_d, out);
    }
}